// round 2
// baseline (speedup 1.0000x reference)
#include <cuda_runtime.h>
#include <cstdint>

// ---------------------------------------------------------------------------
// RowLSTM: x(16,64,64,64), Wi(512,64,1,3), bi(512), Wh(512,128), bh(512)
// out: (16,128,64,64) fp32
// ---------------------------------------------------------------------------

#define B_  16
#define C_  64
#define H_  64
#define W_  64
#define HID_ 128
#define G_  512   // 4*HID
#define K_  192   // C_*3

// scratch
static __device__ float g_i2h[(size_t)H_ * B_ * W_ * G_];   // 134 MB [h][b][w][g]
static __device__ float g_WiT[(size_t)K_ * G_];             // 393 KB [k][g]

// ---- f32x2 helpers ---------------------------------------------------------
__device__ __forceinline__ uint64_t pk2(float a, float b) {
    uint64_t r; asm("mov.b64 %0,{%1,%2};" : "=l"(r) : "f"(a), "f"(b)); return r;
}
__device__ __forceinline__ void upk2(uint64_t v, float& a, float& b) {
    asm("mov.b64 {%0,%1},%2;" : "=f"(a), "=f"(b) : "l"(v));
}
__device__ __forceinline__ uint64_t ffma2(uint64_t a, uint64_t b, uint64_t c) {
    uint64_t d; asm("fma.rn.f32x2 %0,%1,%2,%3;" : "=l"(d) : "l"(a), "l"(b), "l"(c)); return d;
}

// ---------------------------------------------------------------------------
// Kernel 0: transpose Wi -> WiT[k][g]
// ---------------------------------------------------------------------------
__global__ void prep_kernel(const float* __restrict__ Wi)
{
    int k = blockIdx.x;    // 0..191
    int g = threadIdx.x;   // 0..511
    g_WiT[(size_t)k * G_ + g] = Wi[(size_t)g * K_ + k];
}

// ---------------------------------------------------------------------------
// Kernel A: i2h GEMM. One block per (b,h). 512 threads.
// thread: gates g0..g0+7 (g0=(tid&63)*8), cols w0..w0+7 (w0=(tid>>6)*8)
// ---------------------------------------------------------------------------
__global__ void __launch_bounds__(512, 1)
i2h_kernel(const float* __restrict__ x,
           const float* __restrict__ bi, const float* __restrict__ bh)
{
    const int b = blockIdx.x & 15;
    const int h = blockIdx.x >> 4;
    const int tid = threadIdx.x;

    __shared__ float xs[C_][68];       // [c][w+1], zero pad ends
    __shared__ float ws[2][12][G_];    // ping-pong Wi chunks [kk][g]

    // x tile, coalesced
    for (int idx = tid; idx < C_ * W_; idx += 512) {
        int c = idx >> 6, w = idx & 63;
        xs[c][w + 1] = x[((((size_t)b * C_) + c) * H_ + h) * W_ + w];
    }
    if (tid < C_) { xs[tid][0] = 0.f; xs[tid][65] = 0.f; xs[tid][66] = 0.f; xs[tid][67] = 0.f; }

    // stage chunk 0 (coalesced from WiT)
    float r[12];
#pragma unroll
    for (int j = 0; j < 12; j++) r[j] = g_WiT[(size_t)j * G_ + tid];
#pragma unroll
    for (int j = 0; j < 12; j++) ws[0][j][tid] = r[j];
    __syncthreads();

    const int g0 = (tid & 63) * 8;
    const int w0 = (tid >> 6) * 8;

    uint64_t acc2[4][8];   // [gate-pair][col]
#pragma unroll
    for (int i = 0; i < 4; i++)
#pragma unroll
        for (int j = 0; j < 8; j++) acc2[i][j] = 0ull;

    for (int kc = 0; kc < 16; kc++) {
        if (kc < 15) {
#pragma unroll
            for (int j = 0; j < 12; j++)
                r[j] = g_WiT[((size_t)(kc + 1) * 12 + j) * G_ + tid];
        }
        const int buf = kc & 1;

#pragma unroll
        for (int cc = 0; cc < 4; cc++) {
            const int c = kc * 4 + cc;
            const float* xrow = &xs[c][w0];
            float4 xa = *reinterpret_cast<const float4*>(xrow);
            float4 xb = *reinterpret_cast<const float4*>(xrow + 4);
            float4 xc = *reinterpret_cast<const float4*>(xrow + 8);
            float xr[12] = {xa.x, xa.y, xa.z, xa.w,
                            xb.x, xb.y, xb.z, xb.w,
                            xc.x, xc.y, xc.z, xc.w};
            uint64_t xbp[10];
#pragma unroll
            for (int o = 0; o < 10; o++) xbp[o] = pk2(xr[o], xr[o]);

#pragma unroll
            for (int kw = 0; kw < 3; kw++) {
                const int kk = cc * 3 + kw;
                const float* wrow = &ws[buf][kk][g0];
                float4 wa = *reinterpret_cast<const float4*>(wrow);
                float4 wb = *reinterpret_cast<const float4*>(wrow + 4);
                uint64_t wp[4] = {pk2(wa.x, wa.y), pk2(wa.z, wa.w),
                                  pk2(wb.x, wb.y), pk2(wb.z, wb.w)};
#pragma unroll
                for (int i = 0; i < 4; i++)
#pragma unroll
                    for (int j = 0; j < 8; j++)
                        acc2[i][j] = ffma2(wp[i], xbp[j + kw], acc2[i][j]);
            }
        }

        if (kc < 15) {
            const int nb = (kc + 1) & 1;
#pragma unroll
            for (int j = 0; j < 12; j++) ws[nb][j][tid] = r[j];
        }
        __syncthreads();
    }

    float bias[8];
#pragma unroll
    for (int i = 0; i < 8; i++) bias[i] = bi[g0 + i] + bh[g0 + i];

    const size_t obase = ((((size_t)h * B_ + b) * W_) + w0) * G_ + g0;
#pragma unroll
    for (int j = 0; j < 8; j++) {
        float o0, o1, o2, o3, o4, o5, o6, o7;
        upk2(acc2[0][j], o0, o1);
        upk2(acc2[1][j], o2, o3);
        upk2(acc2[2][j], o4, o5);
        upk2(acc2[3][j], o6, o7);
        float4 v0 = make_float4(o0 + bias[0], o1 + bias[1], o2 + bias[2], o3 + bias[3]);
        float4 v1 = make_float4(o4 + bias[4], o5 + bias[5], o6 + bias[6], o7 + bias[7]);
        *reinterpret_cast<float4*>(&g_i2h[obase + (size_t)j * G_])     = v0;
        *reinterpret_cast<float4*>(&g_i2h[obase + (size_t)j * G_ + 4]) = v1;
    }
}

// ---------------------------------------------------------------------------
// Kernel B: recurrent scan. 128 blocks = (b, w-group of 8 cols), 512 threads.
// thread t owns gate row t; h kept in smem as [d][col] so col-pairs load as u64.
// ---------------------------------------------------------------------------
__device__ __forceinline__ float sigmf(float v) {
    return __fdividef(1.0f, 1.0f + __expf(-v));
}
__device__ __forceinline__ float tanhf_(float v) {
    return __fdividef(2.0f, 1.0f + __expf(-2.0f * v)) - 1.0f;
}

__global__ void __launch_bounds__(512, 1)
rec_kernel(const float* __restrict__ Wh, float* __restrict__ out)
{
    const int b  = blockIdx.x >> 3;
    const int w0 = (blockIdx.x & 7) * 8;
    const int t  = threadIdx.x;

    __shared__ float hbuf[HID_][8];    // [d][col]
    __shared__ float cbuf[HID_][8];
    __shared__ float gbuf[8][G_];      // [col][gate]

    for (int p = t; p < HID_ * 8; p += 512) {
        (&hbuf[0][0])[p] = 0.f;
        (&cbuf[0][0])[p] = 0.f;
    }
    __syncthreads();

    const float4* __restrict__ Wh4 = reinterpret_cast<const float4*>(Wh) + (size_t)t * 32;

    for (int row = 0; row < H_; row++) {
        // issue i2h loads early; consumed after the dot
        const float* gp = g_i2h + ((((size_t)row * B_ + b) * W_) + w0) * G_ + t;
        float gv[8];
#pragma unroll
        for (int col = 0; col < 8; col++) gv[col] = __ldg(gp + (size_t)col * G_);

        uint64_t accp[4] = {0ull, 0ull, 0ull, 0ull};   // col pairs (0,1)(2,3)(4,5)(6,7)

#pragma unroll 4
        for (int d4 = 0; d4 < 32; d4++) {
            float4 wv = __ldg(Wh4 + d4);
#pragma unroll
            for (int e = 0; e < 4; e++) {
                const float w = (e == 0) ? wv.x : (e == 1) ? wv.y : (e == 2) ? wv.z : wv.w;
                const uint64_t wp = pk2(w, w);
                const uint64_t* hp = reinterpret_cast<const uint64_t*>(&hbuf[d4 * 4 + e][0]);
                accp[0] = ffma2(wp, hp[0], accp[0]);
                accp[1] = ffma2(wp, hp[1], accp[1]);
                accp[2] = ffma2(wp, hp[2], accp[2]);
                accp[3] = ffma2(wp, hp[3], accp[3]);
            }
        }

#pragma unroll
        for (int q = 0; q < 4; q++) {
            float lo, hi;
            upk2(accp[q], lo, hi);
            gbuf[2 * q][t]     = lo + gv[2 * q];
            gbuf[2 * q + 1][t] = hi + gv[2 * q + 1];
        }
        __syncthreads();

        // pointwise LSTM update: 1024 (col,d) pairs / 512 threads
#pragma unroll
        for (int pp = 0; pp < 2; pp++) {
            int p   = t + pp * 512;
            int col = p >> 7;
            int d   = p & 127;
            float ig = gbuf[col][d];
            float fg = gbuf[col][HID_ + d];
            float og = gbuf[col][2 * HID_ + d];
            float gg = gbuf[col][3 * HID_ + d];
            float cv = sigmf(fg) * cbuf[d][col] + sigmf(ig) * tanhf_(gg);
            float hv = sigmf(og) * tanhf_(cv);
            cbuf[d][col] = cv;
            hbuf[d][col] = hv;
        }
        __syncthreads();

        // output write: out[b][d][row][w0..w0+8)
        if (t < HID_) {
            const int d = t;
            float4 v0 = make_float4(hbuf[d][0], hbuf[d][1], hbuf[d][2], hbuf[d][3]);
            float4 v1 = make_float4(hbuf[d][4], hbuf[d][5], hbuf[d][6], hbuf[d][7]);
            float* op = out + ((((size_t)b * HID_ + d) * H_) + row) * W_ + w0;
            *reinterpret_cast<float4*>(op)     = v0;
            *reinterpret_cast<float4*>(op + 4) = v1;
        }
        // no barrier needed here: next pointwise (hbuf overwrite) is after the
        // next __syncthreads(), and out-write precedes that barrier per-thread.
    }
}

// ---------------------------------------------------------------------------
extern "C" void kernel_launch(void* const* d_in, const int* in_sizes, int n_in,
                              void* d_out, int out_size)
{
    (void)in_sizes; (void)n_in; (void)out_size;
    const float* x  = (const float*)d_in[0];
    const float* Wi = (const float*)d_in[1];
    const float* bi = (const float*)d_in[2];
    const float* Wh = (const float*)d_in[3];
    const float* bh = (const float*)d_in[4];
    float* out = (float*)d_out;

    prep_kernel<<<K_, G_>>>(Wi);
    i2h_kernel<<<B_ * H_, 512>>>(x, bi, bh);
    rec_kernel<<<B_ * (W_ / 8), 512>>>(Wh, out);
}